// round 6
// baseline (speedup 1.0000x reference)
#include <cuda_runtime.h>
#include <cuda_fp16.h>

#define NN      100000
#define NE      1600000
#define NG      1024
#define EMB_D   32
#define HID_D   64
#define NC      10
#define NSH     17          // N_SHAPE+1
#define NCO     9           // N_COLOR+1

#define SCAN_B  256
#define NBLK    ((NN + SCAN_B - 1) / SCAN_B)   // 391

// ---------------- scratch (device globals) ----------------------------------
__device__ __half2 g_h2 [NN * 32];     // hs = h*dis, fp16 (64 halves/node)
__device__ float   g_a  [NN * HID_D];  // layer-1 output / layer-2 input (fp32)
__device__ float   g_dis[NN];
__device__ int     g_ideg[NN];
__device__ int     g_off[NN + 1];      // CSR offsets (exclusive)
__device__ int     g_cur[NN];          // fill cursors
__device__ int     g_bsum[512];
__device__ int     g_csrc[NE];         // CSR src-ids grouped by dst
__device__ float   g_st1[NSH * HID_D]; // shape_table @ W1 (row0 = 0)
__device__ float   g_ct1[NCO * HID_D]; // color_table @ W1 (row0 = 0)
__device__ float   g_pool[NG * HID_D];
__device__ float   g_cnt[NG];

__device__ __forceinline__ void red_v4(float* p, float4 v) {
    asm volatile("red.global.add.v4.f32 [%0], {%1,%2,%3,%4};"
                 :: "l"(p), "f"(v.x), "f"(v.y), "f"(v.z), "f"(v.w) : "memory");
}

// accumulate 8 fp16 values (one uint4) into 8 fp32 accumulators
__device__ __forceinline__ void acc8(float* acc, uint4 u) {
    const __half2* hp = (const __half2*)&u;
#pragma unroll
    for (int q = 0; q < 4; q++) {
        float2 f = __half22float2(hp[q]);
        acc[2 * q]     += f.x;
        acc[2 * q + 1] += f.y;
    }
}

// ---------------- CSR build ---------------------------------------------------

__global__ void k_zero() {
    int i = blockIdx.x * blockDim.x + threadIdx.x;
    if (i < NN) g_ideg[i] = 0;
    if (i < NG * HID_D) g_pool[i] = 0.0f;
    if (i < NG) g_cnt[i] = 0.0f;
}

__global__ void k_deg(const int* __restrict__ dst) {
    int e = blockIdx.x * blockDim.x + threadIdx.x;
    if (e < NE) atomicAdd(&g_ideg[dst[e]], 1);
}

__global__ void k_scan1() {
    __shared__ int s[SCAN_B];
    int i = blockIdx.x * SCAN_B + threadIdx.x;
    int v = (i < NN) ? g_ideg[i] : 0;
    s[threadIdx.x] = v;
    __syncthreads();
    for (int o = 1; o < SCAN_B; o <<= 1) {
        int t = (threadIdx.x >= o) ? s[threadIdx.x - o] : 0;
        __syncthreads();
        s[threadIdx.x] += t;
        __syncthreads();
    }
    if (i < NN) g_off[i] = s[threadIdx.x];
    if (threadIdx.x == SCAN_B - 1) g_bsum[blockIdx.x] = s[SCAN_B - 1];
}

__global__ void k_scan2() {
    __shared__ int s[512];
    int t = threadIdx.x;
    int orig = (t < NBLK) ? g_bsum[t] : 0;
    s[t] = orig;
    __syncthreads();
    for (int o = 1; o < 512; o <<= 1) {
        int v = (t >= o) ? s[t - o] : 0;
        __syncthreads();
        s[t] += v;
        __syncthreads();
    }
    if (t < NBLK) g_bsum[t] = s[t] - orig;
    if (t == 0) g_off[NN] = NE;
}

__global__ void k_scan3() {
    int i = blockIdx.x * SCAN_B + threadIdx.x;
    if (i >= NN) return;
    int v = g_off[i] - g_ideg[i] + g_bsum[blockIdx.x];
    g_off[i] = v;
    g_cur[i] = v;
}

__global__ void k_fill(const int* __restrict__ src, const int* __restrict__ dst) {
    int e = blockIdx.x * blockDim.x + threadIdx.x;
    if (e >= NE) return;
    int p = atomicAdd(&g_cur[dst[e]], 1);
    g_csrc[p] = src[e];
}

// ---------------- side chain: dis/cnt, table precompute, hs1 -----------------

__global__ void k_dis(const int* __restrict__ batch) {
    int i = blockIdx.x * blockDim.x + threadIdx.x;
    if (i >= NN) return;
    g_dis[i] = rsqrtf(1.0f + (float)g_ideg[i]);
    atomicAdd(&g_cnt[batch[i]], 1.0f);
}

// ST1 = shape_table@W1 (row0=0); CT1 = color_table@W1 (row0=0). One block.
__global__ void k_tab1(const float* __restrict__ stab, const float* __restrict__ ctab,
                       const float* __restrict__ W1) {
    __shared__ float sW[EMB_D * HID_D];
    for (int t = threadIdx.x; t < EMB_D * HID_D; t += blockDim.x) sW[t] = W1[t];
    __syncthreads();
    for (int idx = threadIdx.x; idx < (NSH + NCO) * HID_D; idx += blockDim.x) {
        int row = idx / HID_D, j = idx % HID_D;
        const float* tab;
        float* out;
        int r;
        if (row < NSH) { tab = stab; out = g_st1; r = row; }
        else           { tab = ctab; out = g_ct1; r = row - NSH; }
        float s = 0.0f;
        if (r != 0) {
#pragma unroll
            for (int k = 0; k < EMB_D; k++)
                s = fmaf(tab[r * EMB_D + k], sW[k * HID_D + j], s);
        }
        out[r * HID_D + j] = s;
    }
}

// hs1[i] = (ST1[sid]+CT1[cid]) * dis -> g_h2 (fp16). 8 threads/node.
__global__ void k_hs1(const int* __restrict__ sid, const int* __restrict__ cid) {
    int t = blockIdx.x * blockDim.x + threadIdx.x;
    if (t >= NN * 8) return;
    int i = t >> 3, jq = t & 7;
    int s = __ldg(sid + i), c = __ldg(cid + i);
    float d = g_dis[i];
    const float4* S = (const float4*)(g_st1 + s * HID_D + jq * 8);
    const float4* C = (const float4*)(g_ct1 + c * HID_D + jq * 8);
    float4 a0 = S[0], a1 = S[1], c0 = C[0], c1 = C[1];
    __half2 h[4];
    h[0] = __floats2half2_rn((a0.x + c0.x) * d, (a0.y + c0.y) * d);
    h[1] = __floats2half2_rn((a0.z + c0.z) * d, (a0.w + c0.w) * d);
    h[2] = __floats2half2_rn((a1.x + c1.x) * d, (a1.y + c1.y) * d);
    h[3] = __floats2half2_rn((a1.z + c1.z) * d, (a1.w + c1.w) * d);
    ((uint4*)g_h2)[t] = *(const uint4*)h;
}

// ---------------- mm2: hs = (g_a @ W2) * dis -> g_h2 (fp16) ------------------
// 256 threads: 32 nodes x 8 output-groups of 8
__global__ void k_mm2(const float* __restrict__ W2) {
    __shared__ float4 sW[HID_D * 16];   // 64x64 fp32 = 16KB, as float4
    __shared__ float  sx[32 * HID_D];   // 32 node rows, 8KB
    int tid = threadIdx.x;
    int node0 = blockIdx.x * 32;
#pragma unroll
    for (int t = tid; t < HID_D * 16; t += 256) sW[t] = ((const float4*)W2)[t];
    const float4* ga = (const float4*)(g_a + (long)node0 * HID_D);
    ((float4*)sx)[tid]       = ga[tid];
    ((float4*)sx)[tid + 256] = ga[tid + 256];
    __syncthreads();
    int n = tid >> 3, jq = tid & 7;
    int i = node0 + n;
    float acc[8] = {0, 0, 0, 0, 0, 0, 0, 0};
#pragma unroll
    for (int k = 0; k < HID_D; k++) {
        float xk = sx[n * HID_D + k];
        float4 wa = sW[k * 16 + jq * 2];
        float4 wb = sW[k * 16 + jq * 2 + 1];
        acc[0] = fmaf(xk, wa.x, acc[0]);
        acc[1] = fmaf(xk, wa.y, acc[1]);
        acc[2] = fmaf(xk, wa.z, acc[2]);
        acc[3] = fmaf(xk, wa.w, acc[3]);
        acc[4] = fmaf(xk, wb.x, acc[4]);
        acc[5] = fmaf(xk, wb.y, acc[5]);
        acc[6] = fmaf(xk, wb.z, acc[6]);
        acc[7] = fmaf(xk, wb.w, acc[7]);
    }
    float d = g_dis[i];
    __half2 h[4];
#pragma unroll
    for (int q = 0; q < 4; q++)
        h[q] = __floats2half2_rn(acc[2 * q] * d, acc[2 * q + 1] * d);
    ((uint4*)g_h2)[i * 8 + jq] = *(const uint4*)h;
}

// ---------------- CSR gather (fp16 reads, fp32 accum) ------------------------

__device__ __forceinline__ void gather_acc(int i, int jq, float* acc) {
    const uint4* H = (const uint4*)g_h2;
    int beg = g_off[i], end = g_off[i + 1];
    // self-loop seed
    {
        uint4 u = H[i * 8 + jq];
        const __half2* hp = (const __half2*)&u;
#pragma unroll
        for (int q = 0; q < 4; q++) {
            float2 f = __half22float2(hp[q]);
            acc[2 * q] = f.x;
            acc[2 * q + 1] = f.y;
        }
    }
    int e = beg;
    for (; e + 4 <= end; e += 4) {
        int s0 = __ldg(g_csrc + e + 0);
        int s1 = __ldg(g_csrc + e + 1);
        int s2 = __ldg(g_csrc + e + 2);
        int s3 = __ldg(g_csrc + e + 3);
        uint4 u0 = H[s0 * 8 + jq];
        uint4 u1 = H[s1 * 8 + jq];
        uint4 u2 = H[s2 * 8 + jq];
        uint4 u3 = H[s3 * 8 + jq];
        acc8(acc, u0); acc8(acc, u1); acc8(acc, u2); acc8(acc, u3);
    }
    for (; e < end; e++) {
        int s = __ldg(g_csrc + e);
        acc8(acc, H[s * 8 + jq]);
    }
}

__global__ void k_gather1(const float* __restrict__ bias) {
    int t = blockIdx.x * blockDim.x + threadIdx.x;
    if (t >= NN * 8) return;
    int i = t >> 3, jq = t & 7;
    float acc[8];
    gather_acc(i, jq, acc);
    float d = g_dis[i];
    float4 b0 = ((const float4*)bias)[jq * 2];
    float4 b1 = ((const float4*)bias)[jq * 2 + 1];
    const float* bb = (const float*)&b0;  // b0,b1 contiguous? safer: per element
    float4 v0, v1;
    v0.x = fmaxf(fmaf(d, acc[0], b0.x), 0.0f);
    v0.y = fmaxf(fmaf(d, acc[1], b0.y), 0.0f);
    v0.z = fmaxf(fmaf(d, acc[2], b0.z), 0.0f);
    v0.w = fmaxf(fmaf(d, acc[3], b0.w), 0.0f);
    v1.x = fmaxf(fmaf(d, acc[4], b1.x), 0.0f);
    v1.y = fmaxf(fmaf(d, acc[5], b1.y), 0.0f);
    v1.z = fmaxf(fmaf(d, acc[6], b1.z), 0.0f);
    v1.w = fmaxf(fmaf(d, acc[7], b1.w), 0.0f);
    (void)bb;
    float4* out = (float4*)(g_a + (long)i * HID_D + jq * 8);
    out[0] = v0;
    out[1] = v1;
}

__global__ void k_gather2(const float* __restrict__ bias, const int* __restrict__ batch) {
    int t = blockIdx.x * blockDim.x + threadIdx.x;
    if (t >= NN * 8) return;
    int i = t >> 3, jq = t & 7;
    float acc[8];
    gather_acc(i, jq, acc);
    float d = g_dis[i];
    float4 b0 = ((const float4*)bias)[jq * 2];
    float4 b1 = ((const float4*)bias)[jq * 2 + 1];
    float4 v0, v1;
    v0.x = fmaxf(fmaf(d, acc[0], b0.x), 0.0f);
    v0.y = fmaxf(fmaf(d, acc[1], b0.y), 0.0f);
    v0.z = fmaxf(fmaf(d, acc[2], b0.z), 0.0f);
    v0.w = fmaxf(fmaf(d, acc[3], b0.w), 0.0f);
    v1.x = fmaxf(fmaf(d, acc[4], b1.x), 0.0f);
    v1.y = fmaxf(fmaf(d, acc[5], b1.y), 0.0f);
    v1.z = fmaxf(fmaf(d, acc[6], b1.z), 0.0f);
    v1.w = fmaxf(fmaf(d, acc[7], b1.w), 0.0f);
    int bt = __ldg(batch + i);
    red_v4(g_pool + bt * HID_D + jq * 8, v0);
    red_v4(g_pool + bt * HID_D + jq * 8 + 4, v1);
}

__global__ void k_final(const float* __restrict__ Wl, const float* __restrict__ bl,
                        float* __restrict__ out) {
    int idx = blockIdx.x * blockDim.x + threadIdx.x;
    if (idx >= NG * NC) return;
    int b = idx / NC, c = idx % NC;
    float inv = 1.0f / fmaxf(g_cnt[b], 1.0f);
    float s = bl[c];
#pragma unroll
    for (int j = 0; j < HID_D; j++)
        s = fmaf(g_pool[b * HID_D + j] * inv, Wl[j * NC + c], s);
    out[idx] = s;
}

// ---------------- launch ------------------------------------------------------
extern "C" void kernel_launch(void* const* d_in, const int* in_sizes, int n_in,
                              void* d_out, int out_size) {
    const int*   shape_id = (const int*)  d_in[0];
    const int*   color_id = (const int*)  d_in[1];
    const int*   edge     = (const int*)  d_in[2];
    const int*   batch    = (const int*)  d_in[3];
    const float* stab     = (const float*)d_in[4];
    const float* ctab     = (const float*)d_in[5];
    const float* W1       = (const float*)d_in[6];
    const float* b1       = (const float*)d_in[7];
    const float* W2       = (const float*)d_in[8];
    const float* b2       = (const float*)d_in[9];
    const float* Wl       = (const float*)d_in[10];
    const float* bl       = (const float*)d_in[11];
    float*       out      = (float*)d_out;

    const int* src = edge;
    const int* dst = edge + NE;

    const int T = 256;
    auto blk = [](long n, int t) { return (int)((n + t - 1) / t); };

    // one-time stream/event setup (outside capture; first call is the
    // uncaptured correctness run). Work is identical on every call.
    static cudaStream_t side = 0;
    static cudaEvent_t evStart = 0, evDeg = 0, evHs = 0;
    static bool init_done = false;
    if (!init_done) {
        init_done = true;
        if (cudaStreamCreateWithFlags(&side, cudaStreamNonBlocking) != cudaSuccess) side = 0;
        if (cudaEventCreateWithFlags(&evStart, cudaEventDisableTiming) != cudaSuccess) evStart = 0;
        if (cudaEventCreateWithFlags(&evDeg, cudaEventDisableTiming) != cudaSuccess) evDeg = 0;
        if (cudaEventCreateWithFlags(&evHs, cudaEventDisableTiming) != cudaSuccess) evHs = 0;
    }
    bool fork = (side != 0 && evStart && evDeg && evHs);

    if (fork) {
        cudaEventRecord(evStart, 0);
        cudaStreamWaitEvent(side, evStart, 0);

        // main: CSR build
        k_zero <<<blk(NN, T), T>>>();
        k_deg  <<<blk(NE, T), T>>>(dst);
        cudaEventRecord(evDeg, 0);
        k_scan1<<<NBLK, SCAN_B>>>();
        k_scan2<<<1, 512>>>();
        k_scan3<<<NBLK, SCAN_B>>>();
        k_fill <<<blk(NE, T), T>>>(src, dst);

        // side: tab1 (independent), then dis+hs1 after deg (zero happens before deg)
        k_tab1<<<1, 256, 0, side>>>(stab, ctab, W1);
        cudaStreamWaitEvent(side, evDeg, 0);
        k_dis <<<blk(NN, T), T, 0, side>>>(batch);
        k_hs1 <<<blk((long)NN * 8, T), T, 0, side>>>(shape_id, color_id);
        cudaEventRecord(evHs, side);

        cudaStreamWaitEvent(0, evHs, 0);   // join
    } else {
        k_zero <<<blk(NN, T), T>>>();
        k_tab1 <<<1, 256>>>(stab, ctab, W1);
        k_deg  <<<blk(NE, T), T>>>(dst);
        k_dis  <<<blk(NN, T), T>>>(batch);
        k_scan1<<<NBLK, SCAN_B>>>();
        k_scan2<<<1, 512>>>();
        k_scan3<<<NBLK, SCAN_B>>>();
        k_fill <<<blk(NE, T), T>>>(src, dst);
        k_hs1  <<<blk((long)NN * 8, T), T>>>(shape_id, color_id);
    }

    // layer 1
    k_gather1<<<blk((long)NN * 8, T), T>>>(b1);
    // layer 2
    k_mm2    <<<NN / 32, T>>>(W2);
    k_gather2<<<blk((long)NN * 8, T), T>>>(b2, batch);

    k_final<<<blk(NG * NC, T), T>>>(Wl, bl, out);
}